// round 6
// baseline (speedup 1.0000x reference)
#include <cuda_runtime.h>
#include <cuda_bf16.h>
#include <cstdint>

// ============================================================
// Problem constants
// ============================================================
#define N_TOK  262144
#define DDIM   256
#define HDIM   256
#define NEXP   8

// ============================================================
// Device scratch (allocation-free contract: __device__ globals)
// ============================================================
__device__ unsigned      g_cnt[NEXP];
__device__ unsigned      g_dst [NEXP][N_TOK];     // t*2+k per routed row
__device__ float         g_gate[NEXP][N_TOK];     // gate weight per routed row
__device__ __nv_bfloat16 g_xhi[(size_t)N_TOK * DDIM];
__device__ __nv_bfloat16 g_xlo[(size_t)N_TOK * DDIM];
__device__ __nv_bfloat16 g_whi[NEXP * HDIM * DDIM];
__device__ __nv_bfloat16 g_wlo[NEXP * HDIM * DDIM];
__device__ float         g_ybuf[(size_t)N_TOK * 2 * HDIM];   // 512 MB

// ============================================================
// PTX helpers (plain sm_100 ONLY: cp.async, ldmatrix, mma.sync)
// ============================================================
__device__ __forceinline__ uint32_t smem_u32(const void* p) {
    uint32_t a;
    asm("{ .reg .u64 t; cvta.to.shared.u64 t, %1; cvt.u32.u64 %0, t; }" : "=r"(a) : "l"(p));
    return a;
}

#define CP_ASYNC16(dst, src) \
    asm volatile("cp.async.cg.shared.global [%0], [%1], 16;" :: "r"(dst), "l"(src))
#define CP_COMMIT() asm volatile("cp.async.commit_group;" ::: "memory")
#define CP_WAIT(n)  asm volatile("cp.async.wait_group %0;" :: "n"(n) : "memory")

__device__ __forceinline__ void ldsm4(uint32_t addr, uint32_t* r) {
    asm volatile("ldmatrix.sync.aligned.m8n8.x4.shared.b16 {%0,%1,%2,%3}, [%4];"
                 : "=r"(r[0]), "=r"(r[1]), "=r"(r[2]), "=r"(r[3]) : "r"(addr));
}

__device__ __forceinline__ void mma16816(float* c, const uint32_t* a,
                                         uint32_t b0, uint32_t b1) {
    asm volatile(
        "mma.sync.aligned.m16n8k16.row.col.f32.bf16.bf16.f32 "
        "{%0,%1,%2,%3}, {%4,%5,%6,%7}, {%8,%9}, {%0,%1,%2,%3};"
        : "+f"(c[0]), "+f"(c[1]), "+f"(c[2]), "+f"(c[3])
        : "r"(a[0]), "r"(a[1]), "r"(a[2]), "r"(a[3]), "r"(b0), "r"(b1));
}

// ============================================================
// Kernel 0: reset routing counters (graph-replay safe)
// ============================================================
__global__ void reset_kernel() {
    if (threadIdx.x < NEXP) g_cnt[threadIdx.x] = 0u;
}

// ============================================================
// Kernel 1: expert weights fp32 -> bf16 hi/lo
// ============================================================
__global__ void convert_w_kernel(const float* __restrict__ ew) {
    int i = blockIdx.x * 256 + threadIdx.x;           // pair index, total E*H*D/2
    float2 v = ((const float2*)ew)[i];
    __nv_bfloat16 hx = __float2bfloat16(v.x);
    __nv_bfloat16 hy = __float2bfloat16(v.y);
    __nv_bfloat162 hi; hi.x = hx; hi.y = hy;
    __nv_bfloat162 lo;
    lo.x = __float2bfloat16(v.x - __bfloat162float(hx));
    lo.y = __float2bfloat16(v.y - __bfloat162float(hy));
    ((__nv_bfloat162*)g_whi)[i] = hi;
    ((__nv_bfloat162*)g_wlo)[i] = lo;
}

// ============================================================
// Kernel 2: gate + softmax + top-2 routing + x -> bf16 hi/lo
//   one warp per token, 8 warps per block
// ============================================================
__global__ __launch_bounds__(256) void gate_route_kernel(
    const float* __restrict__ x,
    const float* __restrict__ gw,
    const float* __restrict__ gb)
{
    __shared__ float sgw[NEXP * DDIM];
    __shared__ float sgb[NEXP];
    for (int i = threadIdx.x; i < NEXP * DDIM; i += 256) sgw[i] = gw[i];
    if (threadIdx.x < NEXP) sgb[threadIdx.x] = gb[threadIdx.x];
    __syncthreads();

    int warp = threadIdx.x >> 5, lane = threadIdx.x & 31;
    int t = blockIdx.x * 8 + warp;

    const float2* xrow = (const float2*)(x + (size_t)t * DDIM);
    float2 xv[4];
#pragma unroll
    for (int j = 0; j < 4; j++) xv[j] = xrow[j * 32 + lane];

    // x -> bf16 hi/lo (coalesced bf16x2 stores)
    __nv_bfloat162* xh2 = (__nv_bfloat162*)(g_xhi + (size_t)t * DDIM);
    __nv_bfloat162* xl2 = (__nv_bfloat162*)(g_xlo + (size_t)t * DDIM);
#pragma unroll
    for (int j = 0; j < 4; j++) {
        __nv_bfloat16 hx = __float2bfloat16(xv[j].x);
        __nv_bfloat16 hy = __float2bfloat16(xv[j].y);
        __nv_bfloat162 hi; hi.x = hx; hi.y = hy;
        __nv_bfloat162 lo;
        lo.x = __float2bfloat16(xv[j].x - __bfloat162float(hx));
        lo.y = __float2bfloat16(xv[j].y - __bfloat162float(hy));
        xh2[j * 32 + lane] = hi;
        xl2[j * 32 + lane] = lo;
    }

    // logits (fp32)
    float logit[NEXP];
#pragma unroll
    for (int e = 0; e < NEXP; e++) {
        float a = 0.f;
#pragma unroll
        for (int j = 0; j < 4; j++) {
            int c = j * 64 + lane * 2;
            a += xv[j].x * sgw[e * DDIM + c] + xv[j].y * sgw[e * DDIM + c + 1];
        }
#pragma unroll
        for (int o = 16; o; o >>= 1) a += __shfl_xor_sync(0xffffffffu, a, o);
        logit[e] = a + sgb[e];
    }

    // top-2 by logit (monotone with softmax prob; ties -> lowest index)
    int i0 = 0; float b0 = logit[0];
#pragma unroll
    for (int e = 1; e < NEXP; e++) if (logit[e] > b0) { b0 = logit[e]; i0 = e; }
    int i1 = -1; float b1 = -3.4e38f;
#pragma unroll
    for (int e = 0; e < NEXP; e++) if (e != i0 && logit[e] > b1) { b1 = logit[e]; i1 = e; }

    // softmax values for the two winners
    float s = 0.f;
#pragma unroll
    for (int e = 0; e < NEXP; e++) s += expf(logit[e] - b0);
    float inv = 1.f / s;
    float gv0 = expf(logit[i0] - b0) * inv;
    float gv1 = expf(logit[i1] - b0) * inv;

    if (lane == 0) {
        unsigned p0 = atomicAdd(&g_cnt[i0], 1u);
        g_dst [i0][p0] = (unsigned)(t * 2);
        g_gate[i0][p0] = gv0;
        unsigned p1 = atomicAdd(&g_cnt[i1], 1u);
        g_dst [i1][p1] = (unsigned)(t * 2 + 1);
        g_gate[i1][p1] = gv1;
    }
}

// ============================================================
// Kernel 3: routed GEMM (mma.sync m16n8k16 bf16, 3-term split)
//   block = 128 gathered tokens x full H=256, one expert
//   BK = 64 bf16 = 128B rows = one SW128 atom; double-buffered cp.async
//   16 warps (512 thr) in a 4(M) x 4(N) grid; warp tile 32x64
// ============================================================
static constexpr int OFF_DST  = 0;      // 128 u32
static constexpr int OFF_GATE = 512;    // 128 f32
static constexpr int OFF_BIAS = 1024;   // 256 f32
static constexpr int OFF_A    = 2048;   // Ahi0,Ahi1 (16KB ea) then Alo0,Alo1
static constexpr int OFF_B    = 67584;  // Bhi0,Bhi1 (32KB ea) then Blo0,Blo1
static constexpr int SMEM_TOTAL = 198656;
#define GEMM_THREADS 512

__device__ __forceinline__ void load_chunk(uint32_t sbase, int buf, int c, int e,
                                           const unsigned* s_dst)
{
    int tid = threadIdx.x;
    uint32_t a_hi = sbase + OFF_A + buf * 16384;
    uint32_t b_hi = sbase + OFF_B + buf * 32768;

    // A: 128 rows x 128B (hi & lo) = 1024 16B units each
#pragma unroll
    for (int i = 0; i < 2; i++) {
        int u = tid + i * GEMM_THREADS;
        int r = u >> 3, q = u & 7;
        unsigned tok = s_dst[r] >> 1;
        size_t g = (size_t)tok * DDIM + c * 64 + q * 8;
        uint32_t d = a_hi + (uint32_t)(r * 128 + ((q ^ (r & 7)) << 4));
        CP_ASYNC16(d, g_xhi + g);
        CP_ASYNC16(d + 32768, g_xlo + g);
    }
    // B: 256 rows x 128B (hi & lo) = 2048 16B units each
#pragma unroll
    for (int i = 0; i < 4; i++) {
        int u = tid + i * GEMM_THREADS;
        int h = u >> 3, q = u & 7;
        size_t g = (size_t)e * (HDIM * DDIM) + (size_t)h * DDIM + c * 64 + q * 8;
        uint32_t d = b_hi + (uint32_t)(h * 128 + ((q ^ (h & 7)) << 4));
        CP_ASYNC16(d, g_whi + g);
        CP_ASYNC16(d + 65536, g_wlo + g);
    }
}

__global__ __launch_bounds__(GEMM_THREADS, 1) void moe_gemm_kernel(const float* __restrict__ eb)
{
    int e = blockIdx.y;
    unsigned cnt = g_cnt[e];
    unsigned row0 = blockIdx.x * 128u;
    if (row0 >= cnt) return;
    int rows = (int)min(128u, cnt - row0);

    extern __shared__ char smem[];
    uint32_t sbase = smem_u32(smem);
    unsigned* s_dst  = (unsigned*)(smem + OFF_DST);
    float*    s_gate = (float*)(smem + OFF_GATE);
    float*    s_bias = (float*)(smem + OFF_BIAS);

    int tid = threadIdx.x, wid = tid >> 5, lane = tid & 31;

    if (tid < 128) {
        s_dst[tid]  = (tid < rows) ? g_dst[e][row0 + tid] : 0u;
        s_gate[tid] = (tid < rows) ? g_gate[e][row0 + tid] : 0.f;
    }
    if (tid < 256) s_bias[tid] = eb[e * HDIM + tid];
    __syncthreads();

    // pipeline: preload chunk 0,1
    load_chunk(sbase, 0, 0, e, s_dst); CP_COMMIT();
    load_chunk(sbase, 1, 1, e, s_dst); CP_COMMIT();

    // warp tile: 4 (M) x 4 (N) -> 32 rows x 64 cols per warp
    int warp_m = wid & 3;               // 0..3 -> rows 32*warp_m
    int warp_n = wid >> 2;              // 0..3 -> cols 64*warp_n

    // ldmatrix lane address components (PTX fragment layouts)
    int laneA_row = (lane & 7) + (((lane >> 3) & 1) << 3);   // 0..15
    int laneA_q   = (lane >> 4) & 1;
    int laneB_n   = (lane & 7) + (((lane >> 4) & 1) << 3);   // 0..15
    int laneB_q   = (lane >> 3) & 1;

    float acc[2][8][4];
#pragma unroll
    for (int a = 0; a < 2; a++)
#pragma unroll
        for (int b = 0; b < 8; b++)
#pragma unroll
            for (int d = 0; d < 4; d++) acc[a][b][d] = 0.f;

#pragma unroll 1
    for (int c = 0; c < 4; c++) {
        int buf = c & 1;
        if (c == 3) { CP_WAIT(0); } else { CP_WAIT(1); }
        __syncthreads();

        uint32_t aBase = sbase + OFF_A + buf * 16384;
        uint32_t bBase = sbase + OFF_B + buf * 32768;

#pragma unroll
        for (int ks = 0; ks < 4; ks++) {
            // A fragments: 2 m16 frags, hi and lo
            uint32_t ahf[2][4], alf[2][4];
#pragma unroll
            for (int mf = 0; mf < 2; mf++) {
                int r = warp_m * 32 + mf * 16 + laneA_row;
                int q = ks * 2 + laneA_q;
                uint32_t off = (uint32_t)(r * 128 + ((q ^ (r & 7)) << 4));
                ldsm4(aBase + off,          ahf[mf]);
                ldsm4(aBase + 32768 + off,  alf[mf]);
            }
#pragma unroll
            for (int nf = 0; nf < 4; nf++) {         // n16 chunks
                int n = warp_n * 64 + nf * 16 + laneB_n;
                int q = ks * 2 + laneB_q;
                uint32_t off = (uint32_t)(n * 128 + ((q ^ (n & 7)) << 4));
                uint32_t bh[4], bl[4];
                ldsm4(bBase + off,          bh);
                ldsm4(bBase + 65536 + off,  bl);

                // term hh: sweep 4 distinct accum frags before reuse
#pragma unroll
                for (int mf = 0; mf < 2; mf++) {
                    mma16816(acc[mf][2 * nf],     ahf[mf], bh[0], bh[1]);
                    mma16816(acc[mf][2 * nf + 1], ahf[mf], bh[2], bh[3]);
                }
                // term hl (A_hi * B_lo)
#pragma unroll
                for (int mf = 0; mf < 2; mf++) {
                    mma16816(acc[mf][2 * nf],     ahf[mf], bl[0], bl[1]);
                    mma16816(acc[mf][2 * nf + 1], ahf[mf], bl[2], bl[3]);
                }
                // term lh (A_lo * B_hi)
#pragma unroll
                for (int mf = 0; mf < 2; mf++) {
                    mma16816(acc[mf][2 * nf],     alf[mf], bh[0], bh[1]);
                    mma16816(acc[mf][2 * nf + 1], alf[mf], bh[2], bh[3]);
                }
            }
        }
        __syncthreads();
        if (c < 2) { load_chunk(sbase, buf, c + 2, e, s_dst); CP_COMMIT(); }
    }

    // Epilogue: out = gate * (acc + bias); token-slot-ordered store, no atomics
    int grp = lane >> 2, tig = lane & 3;
#pragma unroll
    for (int mf = 0; mf < 2; mf++) {
#pragma unroll
        for (int half = 0; half < 2; half++) {
            int r = warp_m * 32 + mf * 16 + grp + half * 8;
            if (r < rows) {
                unsigned tok2 = s_dst[r];
                float gv = s_gate[r];
                float* dst = g_ybuf + (size_t)tok2 * HDIM;
#pragma unroll
                for (int nf = 0; nf < 8; nf++) {
                    int col = warp_n * 64 + nf * 8 + tig * 2;
                    float2 v;
                    v.x = gv * (acc[mf][nf][half * 2 + 0] + s_bias[col]);
                    v.y = gv * (acc[mf][nf][half * 2 + 1] + s_bias[col + 1]);
                    *(float2*)(dst + col) = v;
                }
            }
        }
    }
}

// ============================================================
// Kernel 4: combine ybuf[2t] + ybuf[2t+1] -> out
// ============================================================
__global__ __launch_bounds__(256) void combine_kernel(float* __restrict__ out)
{
    int idx = blockIdx.x * 256 + threadIdx.x;   // float4 index, total N*H/4
    int t  = idx >> 6;
    int h4 = idx & 63;
    const float4* y = (const float4*)g_ybuf;
    float4 a = y[(size_t)t * 128 + h4];
    float4 b = y[(size_t)t * 128 + 64 + h4];
    float4 o;
    o.x = a.x + b.x; o.y = a.y + b.y; o.z = a.z + b.z; o.w = a.w + b.w;
    ((float4*)out)[idx] = o;
}

// ============================================================
// Launch
// ============================================================
extern "C" void kernel_launch(void* const* d_in, const int* in_sizes, int n_in,
                              void* d_out, int out_size)
{
    const float* x  = (const float*)d_in[0];
    const float* gw = (const float*)d_in[1];
    const float* gb = (const float*)d_in[2];
    const float* ew = (const float*)d_in[3];
    const float* eb = (const float*)d_in[4];
    float* out = (float*)d_out;

    cudaFuncSetAttribute(moe_gemm_kernel,
                         cudaFuncAttributeMaxDynamicSharedMemorySize, SMEM_TOTAL);

    reset_kernel<<<1, 32>>>();
    convert_w_kernel<<<(NEXP * HDIM * DDIM / 2) / 256, 256>>>(ew);
    gate_route_kernel<<<N_TOK / 8, 256>>>(x, gw, gb);
    moe_gemm_kernel<<<dim3(N_TOK / 128, NEXP), GEMM_THREADS, SMEM_TOTAL>>>(eb);
    combine_kernel<<<(N_TOK * HDIM / 4) / 256, 256>>>(out);
}

// round 7
// speedup vs baseline: 1.4697x; 1.4697x over previous
#include <cuda_runtime.h>
#include <cuda_bf16.h>
#include <cstdint>

// ============================================================
// Problem constants
// ============================================================
#define N_TOK  262144
#define DDIM   256
#define HDIM   256
#define NEXP   8
#define NPAIR  28

// ============================================================
// Device scratch (allocation-free contract: __device__ globals)
// ============================================================
__device__ unsigned      g_pcnt[NPAIR];
__device__ unsigned      g_ptok[NPAIR][N_TOK];   // token id per routed row
__device__ float         g_pgp [NPAIR][N_TOK];   // gate of lower-index expert p
__device__ float         g_pgq [NPAIR][N_TOK];   // gate of higher-index expert q
__device__ __nv_bfloat16 g_xhi[(size_t)N_TOK * DDIM];
__device__ __nv_bfloat16 g_xlo[(size_t)N_TOK * DDIM];
__device__ __nv_bfloat16 g_whi[NEXP * HDIM * DDIM];
__device__ __nv_bfloat16 g_wlo[NEXP * HDIM * DDIM];

// pair id -> expert indices
__device__ const int c_pair_p[NPAIR] =
    {0,0,0,0,0,0,0, 1,1,1,1,1,1, 2,2,2,2,2, 3,3,3,3, 4,4,4, 5,5, 6};
__device__ const int c_pair_q[NPAIR] =
    {1,2,3,4,5,6,7, 2,3,4,5,6,7, 3,4,5,6,7, 4,5,6,7, 5,6,7, 6,7, 7};

// ============================================================
// PTX helpers (plain sm_100 ONLY: cp.async, ldmatrix, mma.sync)
// ============================================================
__device__ __forceinline__ uint32_t smem_u32(const void* p) {
    uint32_t a;
    asm("{ .reg .u64 t; cvta.to.shared.u64 t, %1; cvt.u32.u64 %0, t; }" : "=r"(a) : "l"(p));
    return a;
}

#define CP_ASYNC16(dst, src) \
    asm volatile("cp.async.cg.shared.global [%0], [%1], 16;" :: "r"(dst), "l"(src))
#define CP_COMMIT() asm volatile("cp.async.commit_group;" ::: "memory")
#define CP_WAIT(n)  asm volatile("cp.async.wait_group %0;" :: "n"(n) : "memory")

__device__ __forceinline__ void ldsm4(uint32_t addr, uint32_t* r) {
    asm volatile("ldmatrix.sync.aligned.m8n8.x4.shared.b16 {%0,%1,%2,%3}, [%4];"
                 : "=r"(r[0]), "=r"(r[1]), "=r"(r[2]), "=r"(r[3]) : "r"(addr));
}

__device__ __forceinline__ void mma16816(float* c, const uint32_t* a,
                                         uint32_t b0, uint32_t b1) {
    asm volatile(
        "mma.sync.aligned.m16n8k16.row.col.f32.bf16.bf16.f32 "
        "{%0,%1,%2,%3}, {%4,%5,%6,%7}, {%8,%9}, {%0,%1,%2,%3};"
        : "+f"(c[0]), "+f"(c[1]), "+f"(c[2]), "+f"(c[3])
        : "r"(a[0]), "r"(a[1]), "r"(a[2]), "r"(a[3]), "r"(b0), "r"(b1));
}

// ============================================================
// Kernel 0: reset routing counters (graph-replay safe)
// ============================================================
__global__ void reset_kernel() {
    if (threadIdx.x < NPAIR) g_pcnt[threadIdx.x] = 0u;
}

// ============================================================
// Kernel 1: expert weights fp32 -> bf16 hi/lo
// ============================================================
__global__ void convert_w_kernel(const float* __restrict__ ew) {
    int i = blockIdx.x * 256 + threadIdx.x;           // pair index, total E*H*D/2
    float2 v = ((const float2*)ew)[i];
    __nv_bfloat16 hx = __float2bfloat16(v.x);
    __nv_bfloat16 hy = __float2bfloat16(v.y);
    __nv_bfloat162 hi; hi.x = hx; hi.y = hy;
    __nv_bfloat162 lo;
    lo.x = __float2bfloat16(v.x - __bfloat162float(hx));
    lo.y = __float2bfloat16(v.y - __bfloat162float(hy));
    ((__nv_bfloat162*)g_whi)[i] = hi;
    ((__nv_bfloat162*)g_wlo)[i] = lo;
}

// ============================================================
// Kernel 2: gate + softmax + top-2 + pair routing + x -> bf16 hi/lo
//   one warp per token, 8 warps per block
// ============================================================
__global__ __launch_bounds__(256) void gate_route_kernel(
    const float* __restrict__ x,
    const float* __restrict__ gw,
    const float* __restrict__ gb)
{
    __shared__ float sgw[NEXP * DDIM];
    __shared__ float sgb[NEXP];
    for (int i = threadIdx.x; i < NEXP * DDIM; i += 256) sgw[i] = gw[i];
    if (threadIdx.x < NEXP) sgb[threadIdx.x] = gb[threadIdx.x];
    __syncthreads();

    int warp = threadIdx.x >> 5, lane = threadIdx.x & 31;
    int t = blockIdx.x * 8 + warp;

    const float2* xrow = (const float2*)(x + (size_t)t * DDIM);
    float2 xv[4];
#pragma unroll
    for (int j = 0; j < 4; j++) xv[j] = xrow[j * 32 + lane];

    // x -> bf16 hi/lo (coalesced bf16x2 stores)
    __nv_bfloat162* xh2 = (__nv_bfloat162*)(g_xhi + (size_t)t * DDIM);
    __nv_bfloat162* xl2 = (__nv_bfloat162*)(g_xlo + (size_t)t * DDIM);
#pragma unroll
    for (int j = 0; j < 4; j++) {
        __nv_bfloat16 hx = __float2bfloat16(xv[j].x);
        __nv_bfloat16 hy = __float2bfloat16(xv[j].y);
        __nv_bfloat162 hi; hi.x = hx; hi.y = hy;
        __nv_bfloat162 lo;
        lo.x = __float2bfloat16(xv[j].x - __bfloat162float(hx));
        lo.y = __float2bfloat16(xv[j].y - __bfloat162float(hy));
        xh2[j * 32 + lane] = hi;
        xl2[j * 32 + lane] = lo;
    }

    // logits (fp32)
    float logit[NEXP];
#pragma unroll
    for (int e = 0; e < NEXP; e++) {
        float a = 0.f;
#pragma unroll
        for (int j = 0; j < 4; j++) {
            int c = j * 64 + lane * 2;
            a += xv[j].x * sgw[e * DDIM + c] + xv[j].y * sgw[e * DDIM + c + 1];
        }
#pragma unroll
        for (int o = 16; o; o >>= 1) a += __shfl_xor_sync(0xffffffffu, a, o);
        logit[e] = a + sgb[e];
    }

    // top-2 by logit (monotone with softmax prob; ties -> lowest index)
    int i0 = 0; float b0 = logit[0];
#pragma unroll
    for (int e = 1; e < NEXP; e++) if (logit[e] > b0) { b0 = logit[e]; i0 = e; }
    int i1 = -1; float b1 = -3.4e38f;
#pragma unroll
    for (int e = 0; e < NEXP; e++) if (e != i0 && logit[e] > b1) { b1 = logit[e]; i1 = e; }

    // softmax values for the two winners
    float s = 0.f;
#pragma unroll
    for (int e = 0; e < NEXP; e++) s += expf(logit[e] - b0);
    float inv = 1.f / s;
    float gv0 = expf(logit[i0] - b0) * inv;
    float gv1 = expf(logit[i1] - b0) * inv;

    if (lane == 0) {
        int p = min(i0, i1), q = max(i0, i1);
        float gp = (p == i0) ? gv0 : gv1;
        float gq = (p == i0) ? gv1 : gv0;
        int pid = p * 7 - (p * (p - 1)) / 2 + (q - p - 1);
        unsigned pos = atomicAdd(&g_pcnt[pid], 1u);
        g_ptok[pid][pos] = (unsigned)t;
        g_pgp [pid][pos] = gp;
        g_pgq [pid][pos] = gq;
    }
}

// ============================================================
// Kernel 3: pair-fused routed GEMM (mma.sync m16n8k16 bf16, 3-term split)
//   block = 128 tokens sharing expert pair (p,q), full H=256
//   8 K-chunks: chunks 0-3 sweep W_p, 4-7 sweep W_q; between them the
//   accumulators are rescaled by g_p/g_q per row; epilogue writes
//   g_q*acc + g_p*b_p + g_q*b_q straight to out. No ybuf, no combine.
// ============================================================
static constexpr int OFF_TOK  = 0;      // 128 u32
static constexpr int OFF_GP   = 512;    // 128 f32
static constexpr int OFF_GQ   = 1024;   // 128 f32
static constexpr int OFF_BP   = 1536;   // 256 f32
static constexpr int OFF_BQ   = 2560;   // 256 f32
static constexpr int OFF_A    = 4096;   // 2 bufs x (hi 16KB + lo 16KB)
static constexpr int OFF_B    = 69632;  // 2 bufs x (hi 32KB + lo 32KB)
static constexpr int SMEM_TOTAL = 200704;
#define GEMM_THREADS 512
#define MAX_TILES 512                    // 512*128 = 65536 tokens/pair cap

__device__ __forceinline__ void load_chunk(uint32_t sbase, int buf, int kslice, int e,
                                           const unsigned* s_tok)
{
    int tid = threadIdx.x;
    uint32_t a_hi = sbase + OFF_A + buf * 32768;
    uint32_t b_hi = sbase + OFF_B + buf * 65536;

    // A: 128 rows x 128B (hi & lo) = 1024 16B units each
#pragma unroll
    for (int i = 0; i < 2; i++) {
        int u = tid + i * GEMM_THREADS;
        int r = u >> 3, q8 = u & 7;
        unsigned tok = s_tok[r];
        size_t g = (size_t)tok * DDIM + kslice * 64 + q8 * 8;
        uint32_t d = a_hi + (uint32_t)(r * 128 + ((q8 ^ (r & 7)) << 4));
        CP_ASYNC16(d, g_xhi + g);
        CP_ASYNC16(d + 16384, g_xlo + g);
    }
    // B: 256 rows x 128B (hi & lo) = 2048 16B units each
#pragma unroll
    for (int i = 0; i < 4; i++) {
        int u = tid + i * GEMM_THREADS;
        int h = u >> 3, q8 = u & 7;
        size_t g = (size_t)e * (HDIM * DDIM) + (size_t)h * DDIM + kslice * 64 + q8 * 8;
        uint32_t d = b_hi + (uint32_t)(h * 128 + ((q8 ^ (h & 7)) << 4));
        CP_ASYNC16(d, g_whi + g);
        CP_ASYNC16(d + 32768, g_wlo + g);
    }
}

__global__ __launch_bounds__(GEMM_THREADS, 1) void moe_gemm_kernel(
    const float* __restrict__ eb, float* __restrict__ out)
{
    int pid = blockIdx.y;
    unsigned cnt = g_pcnt[pid];
    unsigned row0 = blockIdx.x * 128u;
    if (row0 >= cnt) return;
    int rows = (int)min(128u, cnt - row0);
    int ep = c_pair_p[pid], eq = c_pair_q[pid];

    extern __shared__ char smem[];
    uint32_t sbase = smem_u32(smem);
    unsigned* s_tok = (unsigned*)(smem + OFF_TOK);
    float*    s_gp  = (float*)(smem + OFF_GP);
    float*    s_gq  = (float*)(smem + OFF_GQ);
    float*    s_bp  = (float*)(smem + OFF_BP);
    float*    s_bq  = (float*)(smem + OFF_BQ);

    int tid = threadIdx.x, wid = tid >> 5, lane = tid & 31;

    if (tid < 128) {
        bool v = (tid < rows);
        s_tok[tid] = v ? g_ptok[pid][row0 + tid] : 0u;
        s_gp [tid] = v ? g_pgp[pid][row0 + tid] : 0.f;
        s_gq [tid] = v ? g_pgq[pid][row0 + tid] : 1.f;   // keep ratio finite
    }
    if (tid < 256) {
        s_bp[tid] = eb[ep * HDIM + tid];
        s_bq[tid] = eb[eq * HDIM + tid];
    }
    __syncthreads();

    // pipeline: preload chunk 0,1 (both expert p)
    load_chunk(sbase, 0, 0, ep, s_tok); CP_COMMIT();
    load_chunk(sbase, 1, 1, ep, s_tok); CP_COMMIT();

    // warp tile: 4 (M) x 4 (N) -> 32 rows x 64 cols per warp
    int warp_m = wid & 3;
    int warp_n = wid >> 2;

    // ldmatrix lane address components (PTX fragment layouts)
    int laneA_row = (lane & 7) + (((lane >> 3) & 1) << 3);
    int laneA_q   = (lane >> 4) & 1;
    int laneB_n   = (lane & 7) + (((lane >> 4) & 1) << 3);
    int laneB_q   = (lane >> 3) & 1;
    int grp = lane >> 2, tig = lane & 3;

    float acc[2][8][4];
#pragma unroll
    for (int a = 0; a < 2; a++)
#pragma unroll
        for (int b = 0; b < 8; b++)
#pragma unroll
            for (int d = 0; d < 4; d++) acc[a][b][d] = 0.f;

#pragma unroll 1
    for (int c = 0; c < 8; c++) {
        int buf = c & 1;
        if (c == 7) { CP_WAIT(0); } else { CP_WAIT(1); }
        __syncthreads();

        uint32_t aBase = sbase + OFF_A + buf * 32768;
        uint32_t bBase = sbase + OFF_B + buf * 65536;

#pragma unroll
        for (int ks = 0; ks < 4; ks++) {
            uint32_t ahf[2][4], alf[2][4];
#pragma unroll
            for (int mf = 0; mf < 2; mf++) {
                int r = warp_m * 32 + mf * 16 + laneA_row;
                int q8 = ks * 2 + laneA_q;
                uint32_t off = (uint32_t)(r * 128 + ((q8 ^ (r & 7)) << 4));
                ldsm4(aBase + off,          ahf[mf]);
                ldsm4(aBase + 16384 + off,  alf[mf]);
            }
#pragma unroll
            for (int nf = 0; nf < 4; nf++) {
                int n = warp_n * 64 + nf * 16 + laneB_n;
                int q8 = ks * 2 + laneB_q;
                uint32_t off = (uint32_t)(n * 128 + ((q8 ^ (n & 7)) << 4));
                uint32_t bh[4], bl[4];
                ldsm4(bBase + off,          bh);
                ldsm4(bBase + 32768 + off,  bl);

#pragma unroll
                for (int mf = 0; mf < 2; mf++) {
                    mma16816(acc[mf][2 * nf],     ahf[mf], bh[0], bh[1]);
                    mma16816(acc[mf][2 * nf + 1], ahf[mf], bh[2], bh[3]);
                }
#pragma unroll
                for (int mf = 0; mf < 2; mf++) {
                    mma16816(acc[mf][2 * nf],     ahf[mf], bl[0], bl[1]);
                    mma16816(acc[mf][2 * nf + 1], ahf[mf], bl[2], bl[3]);
                }
#pragma unroll
                for (int mf = 0; mf < 2; mf++) {
                    mma16816(acc[mf][2 * nf],     alf[mf], bh[0], bh[1]);
                    mma16816(acc[mf][2 * nf + 1], alf[mf], bh[2], bh[3]);
                }
            }
        }

        // Between the two expert sweeps: acc *= g_p/g_q per row
        if (c == 3) {
#pragma unroll
            for (int mf = 0; mf < 2; mf++) {
#pragma unroll
                for (int half = 0; half < 2; half++) {
                    int r = warp_m * 32 + mf * 16 + grp + half * 8;
                    float f = s_gp[r] / s_gq[r];
#pragma unroll
                    for (int nf = 0; nf < 8; nf++) {
                        acc[mf][nf][half * 2 + 0] *= f;
                        acc[mf][nf][half * 2 + 1] *= f;
                    }
                }
            }
        }

        __syncthreads();
        if (c < 6) {
            int nc = c + 2;
            load_chunk(sbase, buf, nc & 3, (nc < 4) ? ep : eq, s_tok);
            CP_COMMIT();
        }
    }

    // Epilogue: out[tok] = g_q*acc + g_p*b_p + g_q*b_q  (direct, no ybuf)
#pragma unroll
    for (int mf = 0; mf < 2; mf++) {
#pragma unroll
        for (int half = 0; half < 2; half++) {
            int r = warp_m * 32 + mf * 16 + grp + half * 8;
            if (r < rows) {
                unsigned tok = s_tok[r];
                float gq = s_gq[r], gp = s_gp[r];
                float* dst = out + (size_t)tok * HDIM;
#pragma unroll
                for (int nf = 0; nf < 8; nf++) {
                    int col = warp_n * 64 + nf * 8 + tig * 2;
                    float2 v;
                    v.x = gq * acc[mf][nf][half * 2 + 0] + gp * s_bp[col]     + gq * s_bq[col];
                    v.y = gq * acc[mf][nf][half * 2 + 1] + gp * s_bp[col + 1] + gq * s_bq[col + 1];
                    *(float2*)(dst + col) = v;
                }
            }
        }
    }
}

// ============================================================
// Launch
// ============================================================
extern "C" void kernel_launch(void* const* d_in, const int* in_sizes, int n_in,
                              void* d_out, int out_size)
{
    const float* x  = (const float*)d_in[0];
    const float* gw = (const float*)d_in[1];
    const float* gb = (const float*)d_in[2];
    const float* ew = (const float*)d_in[3];
    const float* eb = (const float*)d_in[4];
    float* out = (float*)d_out;

    cudaFuncSetAttribute(moe_gemm_kernel,
                         cudaFuncAttributeMaxDynamicSharedMemorySize, SMEM_TOTAL);

    reset_kernel<<<1, 32>>>();
    convert_w_kernel<<<(NEXP * HDIM * DDIM / 2) / 256, 256>>>(ew);
    gate_route_kernel<<<N_TOK / 8, 256>>>(x, gw, gb);
    moe_gemm_kernel<<<dim3(MAX_TILES, NPAIR), GEMM_THREADS, SMEM_TOTAL>>>(eb, out);
}

// round 8
// speedup vs baseline: 2.3129x; 1.5737x over previous
#include <cuda_runtime.h>
#include <cuda_fp16.h>
#include <cstdint>

// ============================================================
// Problem constants
// ============================================================
#define N_TOK  262144
#define DDIM   256
#define HDIM   256
#define NEXP   8
#define NPAIR  28

// ============================================================
// Device scratch (allocation-free contract: __device__ globals)
// ============================================================
__device__ unsigned g_pcnt[NPAIR];
__device__ unsigned g_ptok[NPAIR][N_TOK];   // token id per routed row
__device__ float    g_pgp [NPAIR][N_TOK];   // gate of lower-index expert p
__device__ float    g_pgq [NPAIR][N_TOK];   // gate of higher-index expert q
__device__ __half   g_xh[(size_t)N_TOK * DDIM];      // x in fp16
__device__ __half   g_wh[NEXP * HDIM * DDIM];        // W in fp16

// pair id -> expert indices
__device__ const int c_pair_p[NPAIR] =
    {0,0,0,0,0,0,0, 1,1,1,1,1,1, 2,2,2,2,2, 3,3,3,3, 4,4,4, 5,5, 6};
__device__ const int c_pair_q[NPAIR] =
    {1,2,3,4,5,6,7, 2,3,4,5,6,7, 3,4,5,6,7, 4,5,6,7, 5,6,7, 6,7, 7};

// ============================================================
// PTX helpers (plain sm_100 ONLY: cp.async, ldmatrix, mma.sync)
// ============================================================
__device__ __forceinline__ uint32_t smem_u32(const void* p) {
    uint32_t a;
    asm("{ .reg .u64 t; cvta.to.shared.u64 t, %1; cvt.u32.u64 %0, t; }" : "=r"(a) : "l"(p));
    return a;
}

#define CP_ASYNC16(dst, src) \
    asm volatile("cp.async.cg.shared.global [%0], [%1], 16;" :: "r"(dst), "l"(src))
#define CP_COMMIT() asm volatile("cp.async.commit_group;" ::: "memory")
#define CP_WAIT(n)  asm volatile("cp.async.wait_group %0;" :: "n"(n) : "memory")

__device__ __forceinline__ void ldsm4(uint32_t addr, uint32_t* r) {
    asm volatile("ldmatrix.sync.aligned.m8n8.x4.shared.b16 {%0,%1,%2,%3}, [%4];"
                 : "=r"(r[0]), "=r"(r[1]), "=r"(r[2]), "=r"(r[3]) : "r"(addr));
}

__device__ __forceinline__ void mma16816(float* c, const uint32_t* a,
                                         uint32_t b0, uint32_t b1) {
    asm volatile(
        "mma.sync.aligned.m16n8k16.row.col.f32.f16.f16.f32 "
        "{%0,%1,%2,%3}, {%4,%5,%6,%7}, {%8,%9}, {%0,%1,%2,%3};"
        : "+f"(c[0]), "+f"(c[1]), "+f"(c[2]), "+f"(c[3])
        : "r"(a[0]), "r"(a[1]), "r"(a[2]), "r"(a[3]), "r"(b0), "r"(b1));
}

// ============================================================
// Kernel 0: reset routing counters (graph-replay safe)
// ============================================================
__global__ void reset_kernel() {
    if (threadIdx.x < NPAIR) g_pcnt[threadIdx.x] = 0u;
}

// ============================================================
// Kernel 1: expert weights fp32 -> fp16
// ============================================================
__global__ void convert_w_kernel(const float* __restrict__ ew) {
    int i = blockIdx.x * 256 + threadIdx.x;           // pair index, total E*H*D/2
    float2 v = ((const float2*)ew)[i];
    __half2 h;
    h.x = __float2half_rn(v.x);
    h.y = __float2half_rn(v.y);
    ((__half2*)g_wh)[i] = h;
}

// ============================================================
// Kernel 2: gate + softmax + top-2 + pair routing + x -> fp16
//   one warp per token, 8 warps per block
// ============================================================
__global__ __launch_bounds__(256) void gate_route_kernel(
    const float* __restrict__ x,
    const float* __restrict__ gw,
    const float* __restrict__ gb)
{
    __shared__ float sgw[NEXP * DDIM];
    __shared__ float sgb[NEXP];
    for (int i = threadIdx.x; i < NEXP * DDIM; i += 256) sgw[i] = gw[i];
    if (threadIdx.x < NEXP) sgb[threadIdx.x] = gb[threadIdx.x];
    __syncthreads();

    int warp = threadIdx.x >> 5, lane = threadIdx.x & 31;
    int t = blockIdx.x * 8 + warp;

    const float2* xrow = (const float2*)(x + (size_t)t * DDIM);
    float2 xv[4];
#pragma unroll
    for (int j = 0; j < 4; j++) xv[j] = xrow[j * 32 + lane];

    // x -> fp16 (coalesced half2 stores)
    __half2* xh2 = (__half2*)(g_xh + (size_t)t * DDIM);
#pragma unroll
    for (int j = 0; j < 4; j++) {
        __half2 h;
        h.x = __float2half_rn(xv[j].x);
        h.y = __float2half_rn(xv[j].y);
        xh2[j * 32 + lane] = h;
    }

    // logits (fp32)
    float logit[NEXP];
#pragma unroll
    for (int e = 0; e < NEXP; e++) {
        float a = 0.f;
#pragma unroll
        for (int j = 0; j < 4; j++) {
            int c = j * 64 + lane * 2;
            a += xv[j].x * sgw[e * DDIM + c] + xv[j].y * sgw[e * DDIM + c + 1];
        }
#pragma unroll
        for (int o = 16; o; o >>= 1) a += __shfl_xor_sync(0xffffffffu, a, o);
        logit[e] = a + sgb[e];
    }

    // top-2 by logit (monotone with softmax prob; ties -> lowest index)
    int i0 = 0; float b0 = logit[0];
#pragma unroll
    for (int e = 1; e < NEXP; e++) if (logit[e] > b0) { b0 = logit[e]; i0 = e; }
    int i1 = -1; float b1 = -3.4e38f;
#pragma unroll
    for (int e = 0; e < NEXP; e++) if (e != i0 && logit[e] > b1) { b1 = logit[e]; i1 = e; }

    // softmax values for the two winners
    float s = 0.f;
#pragma unroll
    for (int e = 0; e < NEXP; e++) s += expf(logit[e] - b0);
    float inv = 1.f / s;
    float gv0 = expf(logit[i0] - b0) * inv;
    float gv1 = expf(logit[i1] - b0) * inv;

    if (lane == 0) {
        int p = min(i0, i1), q = max(i0, i1);
        float gp = (p == i0) ? gv0 : gv1;
        float gq = (p == i0) ? gv1 : gv0;
        int pid = p * 7 - (p * (p - 1)) / 2 + (q - p - 1);
        unsigned pos = atomicAdd(&g_pcnt[pid], 1u);
        g_ptok[pid][pos] = (unsigned)t;
        g_pgp [pid][pos] = gp;
        g_pgq [pid][pos] = gq;
    }
}

// ============================================================
// Kernel 3: pair-fused routed GEMM, single-term fp16 mma.sync
//   block = 128 tokens sharing expert pair (p,q), full H=256
//   8 K-chunks (BK=64): 0-3 sweep W_p, 4-7 sweep W_q; accumulators
//   rescaled by g_p/g_q between sweeps; epilogue writes
//   g_q*acc + g_p*b_p + g_q*b_q straight to out.
//   3-stage cp.async pipeline; SW128-swizzled smem.
// ============================================================
static constexpr int OFF_TOK  = 0;      // 128 u32
static constexpr int OFF_GP   = 512;    // 128 f32
static constexpr int OFF_GQ   = 1024;   // 128 f32
static constexpr int OFF_BP   = 1536;   // 256 f32
static constexpr int OFF_BQ   = 2560;   // 256 f32
static constexpr int OFF_A    = 4096;   // 3 bufs x 16KB
static constexpr int OFF_B    = 53248;  // 3 bufs x 32KB
static constexpr int SMEM_TOTAL = 151552;
#define GEMM_THREADS 512
#define MAX_TILES 512                    // 512*128 = 65536 tokens/pair cap

__device__ __forceinline__ void load_chunk(uint32_t sbase, int buf, int kslice, int e,
                                           const unsigned* s_tok)
{
    int tid = threadIdx.x;
    uint32_t a_s = sbase + OFF_A + buf * 16384;
    uint32_t b_s = sbase + OFF_B + buf * 32768;

    // A: 128 rows x 128B = 1024 16B units
#pragma unroll
    for (int i = 0; i < 2; i++) {
        int u = tid + i * GEMM_THREADS;
        int r = u >> 3, q8 = u & 7;
        unsigned tok = s_tok[r];
        size_t g = (size_t)tok * DDIM + kslice * 64 + q8 * 8;
        uint32_t d = a_s + (uint32_t)(r * 128 + ((q8 ^ (r & 7)) << 4));
        CP_ASYNC16(d, g_xh + g);
    }
    // B: 256 rows x 128B = 2048 16B units
#pragma unroll
    for (int i = 0; i < 4; i++) {
        int u = tid + i * GEMM_THREADS;
        int h = u >> 3, q8 = u & 7;
        size_t g = (size_t)e * (HDIM * DDIM) + (size_t)h * DDIM + kslice * 64 + q8 * 8;
        uint32_t d = b_s + (uint32_t)(h * 128 + ((q8 ^ (h & 7)) << 4));
        CP_ASYNC16(d, g_wh + g);
    }
}

__global__ __launch_bounds__(GEMM_THREADS, 1) void moe_gemm_kernel(
    const float* __restrict__ eb, float* __restrict__ out)
{
    int pid = blockIdx.y;
    unsigned cnt = g_pcnt[pid];
    unsigned row0 = blockIdx.x * 128u;
    if (row0 >= cnt) return;
    int rows = (int)min(128u, cnt - row0);
    int ep = c_pair_p[pid], eq = c_pair_q[pid];

    extern __shared__ char smem[];
    uint32_t sbase = smem_u32(smem);
    unsigned* s_tok = (unsigned*)(smem + OFF_TOK);
    float*    s_gp  = (float*)(smem + OFF_GP);
    float*    s_gq  = (float*)(smem + OFF_GQ);
    float*    s_bp  = (float*)(smem + OFF_BP);
    float*    s_bq  = (float*)(smem + OFF_BQ);

    int tid = threadIdx.x, wid = tid >> 5, lane = tid & 31;

    if (tid < 128) {
        bool v = (tid < rows);
        s_tok[tid] = v ? g_ptok[pid][row0 + tid] : 0u;
        s_gp [tid] = v ? g_pgp[pid][row0 + tid] : 0.f;
        s_gq [tid] = v ? g_pgq[pid][row0 + tid] : 1.f;   // keep ratio finite
    }
    if (tid < 256) {
        s_bp[tid] = eb[ep * HDIM + tid];
        s_bq[tid] = eb[eq * HDIM + tid];
    }
    __syncthreads();

    // 3-stage pipeline: preload chunks 0,1,2 (expert p)
    load_chunk(sbase, 0, 0, ep, s_tok); CP_COMMIT();
    load_chunk(sbase, 1, 1, ep, s_tok); CP_COMMIT();
    load_chunk(sbase, 2, 2, ep, s_tok); CP_COMMIT();

    // warp tile: 4 (M) x 4 (N) -> 32 rows x 64 cols per warp
    int warp_m = wid & 3;
    int warp_n = wid >> 2;

    // ldmatrix lane address components (PTX fragment layouts)
    int laneA_row = (lane & 7) + (((lane >> 3) & 1) << 3);
    int laneA_q   = (lane >> 4) & 1;
    int laneB_n   = (lane & 7) + (((lane >> 4) & 1) << 3);
    int laneB_q   = (lane >> 3) & 1;
    int grp = lane >> 2, tig = lane & 3;

    float acc[2][8][4];
#pragma unroll
    for (int a = 0; a < 2; a++)
#pragma unroll
        for (int b = 0; b < 8; b++)
#pragma unroll
            for (int d = 0; d < 4; d++) acc[a][b][d] = 0.f;

#pragma unroll 1
    for (int c = 0; c < 8; c++) {
        int buf = c % 3;
        if (c >= 6) { CP_WAIT(0); } else { CP_WAIT(2); }
        __syncthreads();

        uint32_t aBase = sbase + OFF_A + buf * 16384;
        uint32_t bBase = sbase + OFF_B + buf * 32768;

#pragma unroll
        for (int ks = 0; ks < 4; ks++) {
            uint32_t ahf[2][4];
#pragma unroll
            for (int mf = 0; mf < 2; mf++) {
                int r = warp_m * 32 + mf * 16 + laneA_row;
                int q8 = ks * 2 + laneA_q;
                uint32_t off = (uint32_t)(r * 128 + ((q8 ^ (r & 7)) << 4));
                ldsm4(aBase + off, ahf[mf]);
            }
#pragma unroll
            for (int nf = 0; nf < 4; nf++) {
                int n = warp_n * 64 + nf * 16 + laneB_n;
                int q8 = ks * 2 + laneB_q;
                uint32_t off = (uint32_t)(n * 128 + ((q8 ^ (n & 7)) << 4));
                uint32_t bh[4];
                ldsm4(bBase + off, bh);
#pragma unroll
                for (int mf = 0; mf < 2; mf++) {
                    mma16816(acc[mf][2 * nf],     ahf[mf], bh[0], bh[1]);
                    mma16816(acc[mf][2 * nf + 1], ahf[mf], bh[2], bh[3]);
                }
            }
        }

        // Between the two expert sweeps: acc *= g_p/g_q per row
        if (c == 3) {
#pragma unroll
            for (int mf = 0; mf < 2; mf++) {
#pragma unroll
                for (int half = 0; half < 2; half++) {
                    int r = warp_m * 32 + mf * 16 + grp + half * 8;
                    float f = s_gp[r] / s_gq[r];
#pragma unroll
                    for (int nf = 0; nf < 8; nf++) {
                        acc[mf][nf][half * 2 + 0] *= f;
                        acc[mf][nf][half * 2 + 1] *= f;
                    }
                }
            }
        }

        __syncthreads();
        if (c < 5) {
            int nc = c + 3;
            load_chunk(sbase, buf, nc & 3, (nc < 4) ? ep : eq, s_tok);
            CP_COMMIT();
        }
    }

    // Epilogue: out[tok] = g_q*acc + g_p*b_p + g_q*b_q  (direct)
#pragma unroll
    for (int mf = 0; mf < 2; mf++) {
#pragma unroll
        for (int half = 0; half < 2; half++) {
            int r = warp_m * 32 + mf * 16 + grp + half * 8;
            if (r < rows) {
                unsigned tok = s_tok[r];
                float gq = s_gq[r], gp = s_gp[r];
                float* dst = out + (size_t)tok * HDIM;
#pragma unroll
                for (int nf = 0; nf < 8; nf++) {
                    int col = warp_n * 64 + nf * 8 + tig * 2;
                    float2 v;
                    v.x = gq * acc[mf][nf][half * 2 + 0] + gp * s_bp[col]     + gq * s_bq[col];
                    v.y = gq * acc[mf][nf][half * 2 + 1] + gp * s_bp[col + 1] + gq * s_bq[col + 1];
                    *(float2*)(dst + col) = v;
                }
            }
        }
    }
}

// ============================================================
// Launch
// ============================================================
extern "C" void kernel_launch(void* const* d_in, const int* in_sizes, int n_in,
                              void* d_out, int out_size)
{
    const float* x  = (const float*)d_in[0];
    const float* gw = (const float*)d_in[1];
    const float* gb = (const float*)d_in[2];
    const float* ew = (const float*)d_in[3];
    const float* eb = (const float*)d_in[4];
    float* out = (float*)d_out;

    cudaFuncSetAttribute(moe_gemm_kernel,
                         cudaFuncAttributeMaxDynamicSharedMemorySize, SMEM_TOTAL);

    reset_kernel<<<1, 32>>>();
    convert_w_kernel<<<(NEXP * HDIM * DDIM / 2) / 256, 256>>>(ew);
    gate_route_kernel<<<N_TOK / 8, 256>>>(x, gw, gb);
    moe_gemm_kernel<<<dim3(MAX_TILES, NPAIR), GEMM_THREADS, SMEM_TOTAL>>>(eb, out);
}

// round 9
// speedup vs baseline: 2.3733x; 1.0261x over previous
#include <cuda_runtime.h>
#include <cuda_fp16.h>
#include <cstdint>

// ============================================================
// Problem constants
// ============================================================
#define N_TOK  262144
#define DDIM   256
#define HDIM   256
#define NEXP   8
#define NPAIR  28

// ============================================================
// Device scratch (allocation-free contract: __device__ globals)
// ============================================================
__device__ unsigned g_pcnt[NPAIR];
__device__ unsigned g_ptok[NPAIR][N_TOK];   // token id per routed row
__device__ float    g_pgp [NPAIR][N_TOK];   // gate of lower-index expert p
__device__ float    g_pgq [NPAIR][N_TOK];   // gate of higher-index expert q
__device__ __half   g_xh[(size_t)N_TOK * DDIM];      // x in fp16
__device__ __half   g_wh[NEXP * HDIM * DDIM];        // W in fp16

// pair id -> expert indices
__device__ const int c_pair_p[NPAIR] =
    {0,0,0,0,0,0,0, 1,1,1,1,1,1, 2,2,2,2,2, 3,3,3,3, 4,4,4, 5,5, 6};
__device__ const int c_pair_q[NPAIR] =
    {1,2,3,4,5,6,7, 2,3,4,5,6,7, 3,4,5,6,7, 4,5,6,7, 5,6,7, 6,7, 7};

// ============================================================
// PTX helpers (plain sm_100 ONLY: cp.async, ldmatrix, mma.sync)
// ============================================================
__device__ __forceinline__ uint32_t smem_u32(const void* p) {
    uint32_t a;
    asm("{ .reg .u64 t; cvta.to.shared.u64 t, %1; cvt.u32.u64 %0, t; }" : "=r"(a) : "l"(p));
    return a;
}

#define CP_ASYNC16(dst, src) \
    asm volatile("cp.async.cg.shared.global [%0], [%1], 16;" :: "r"(dst), "l"(src))
#define CP_COMMIT() asm volatile("cp.async.commit_group;" ::: "memory")
#define CP_WAIT(n)  asm volatile("cp.async.wait_group %0;" :: "n"(n) : "memory")

__device__ __forceinline__ void ldsm4(uint32_t addr, uint32_t* r) {
    asm volatile("ldmatrix.sync.aligned.m8n8.x4.shared.b16 {%0,%1,%2,%3}, [%4];"
                 : "=r"(r[0]), "=r"(r[1]), "=r"(r[2]), "=r"(r[3]) : "r"(addr));
}

__device__ __forceinline__ void mma16816(float* c, const uint32_t* a,
                                         uint32_t b0, uint32_t b1) {
    asm volatile(
        "mma.sync.aligned.m16n8k16.row.col.f32.f16.f16.f32 "
        "{%0,%1,%2,%3}, {%4,%5,%6,%7}, {%8,%9}, {%0,%1,%2,%3};"
        : "+f"(c[0]), "+f"(c[1]), "+f"(c[2]), "+f"(c[3])
        : "r"(a[0]), "r"(a[1]), "r"(a[2]), "r"(a[3]), "r"(b0), "r"(b1));
}

// ============================================================
// Kernel 0: reset routing counters (graph-replay safe)
// ============================================================
__global__ void reset_kernel() {
    if (threadIdx.x < NPAIR) g_pcnt[threadIdx.x] = 0u;
}

// ============================================================
// Kernel 1: expert weights fp32 -> fp16
// ============================================================
__global__ void convert_w_kernel(const float* __restrict__ ew) {
    int i = blockIdx.x * 256 + threadIdx.x;           // pair index, total E*H*D/2
    float2 v = ((const float2*)ew)[i];
    __half2 h;
    h.x = __float2half_rn(v.x);
    h.y = __float2half_rn(v.y);
    ((__half2*)g_wh)[i] = h;
}

// ============================================================
// Kernel 2: gate + softmax + top-2 + pair routing + x -> fp16
//   one warp per token, 8 warps per block
// ============================================================
__global__ __launch_bounds__(256) void gate_route_kernel(
    const float* __restrict__ x,
    const float* __restrict__ gw,
    const float* __restrict__ gb)
{
    __shared__ float sgw[NEXP * DDIM];
    __shared__ float sgb[NEXP];
    for (int i = threadIdx.x; i < NEXP * DDIM; i += 256) sgw[i] = gw[i];
    if (threadIdx.x < NEXP) sgb[threadIdx.x] = gb[threadIdx.x];
    __syncthreads();

    int warp = threadIdx.x >> 5, lane = threadIdx.x & 31;
    int t = blockIdx.x * 8 + warp;

    const float2* xrow = (const float2*)(x + (size_t)t * DDIM);
    float2 xv[4];
#pragma unroll
    for (int j = 0; j < 4; j++) xv[j] = xrow[j * 32 + lane];

    // x -> fp16 (coalesced half2 stores)
    __half2* xh2 = (__half2*)(g_xh + (size_t)t * DDIM);
#pragma unroll
    for (int j = 0; j < 4; j++) {
        __half2 h;
        h.x = __float2half_rn(xv[j].x);
        h.y = __float2half_rn(xv[j].y);
        xh2[j * 32 + lane] = h;
    }

    // logits (fp32)
    float logit[NEXP];
#pragma unroll
    for (int e = 0; e < NEXP; e++) {
        float a = 0.f;
#pragma unroll
        for (int j = 0; j < 4; j++) {
            int c = j * 64 + lane * 2;
            a += xv[j].x * sgw[e * DDIM + c] + xv[j].y * sgw[e * DDIM + c + 1];
        }
#pragma unroll
        for (int o = 16; o; o >>= 1) a += __shfl_xor_sync(0xffffffffu, a, o);
        logit[e] = a + sgb[e];
    }

    // top-2 by logit (monotone with softmax prob; ties -> lowest index)
    int i0 = 0; float b0 = logit[0];
#pragma unroll
    for (int e = 1; e < NEXP; e++) if (logit[e] > b0) { b0 = logit[e]; i0 = e; }
    int i1 = -1; float b1 = -3.4e38f;
#pragma unroll
    for (int e = 0; e < NEXP; e++) if (e != i0 && logit[e] > b1) { b1 = logit[e]; i1 = e; }

    // softmax values for the two winners
    float s = 0.f;
#pragma unroll
    for (int e = 0; e < NEXP; e++) s += expf(logit[e] - b0);
    float inv = 1.f / s;
    float gv0 = expf(logit[i0] - b0) * inv;
    float gv1 = expf(logit[i1] - b0) * inv;

    if (lane == 0) {
        int p = min(i0, i1), q = max(i0, i1);
        float gp = (p == i0) ? gv0 : gv1;
        float gq = (p == i0) ? gv1 : gv0;
        int pid = p * 7 - (p * (p - 1)) / 2 + (q - p - 1);
        unsigned pos = atomicAdd(&g_pcnt[pid], 1u);
        g_ptok[pid][pos] = (unsigned)t;
        g_pgp [pid][pos] = gp;
        g_pgq [pid][pos] = gq;
    }
}

// ============================================================
// Kernel 3: pair-fused routed GEMM, single-term fp16 mma.sync
//   block = 128 tokens sharing expert pair (p,q), full H=256
//   8 K-chunks (BK=64): 0-3 sweep W_p, 4-7 sweep W_q; accumulators
//   rescaled by g_p/g_q between sweeps; epilogue writes
//   g_q*acc + g_p*b_p + g_q*b_q straight to out.
//   8 warps (256 thr), warp tile 64x64: 8 LDSM : 32 HMMA per ks
//   3-stage cp.async pipeline; SW128-swizzled smem.
// ============================================================
static constexpr int OFF_TOK  = 0;      // 128 u32
static constexpr int OFF_GP   = 512;    // 128 f32
static constexpr int OFF_GQ   = 1024;   // 128 f32
static constexpr int OFF_BP   = 1536;   // 256 f32
static constexpr int OFF_BQ   = 2560;   // 256 f32
static constexpr int OFF_A    = 4096;   // 3 bufs x 16KB
static constexpr int OFF_B    = 53248;  // 3 bufs x 32KB
static constexpr int SMEM_TOTAL = 151552;
#define GEMM_THREADS 256
#define MAX_TILES 512                    // 512*128 = 65536 tokens/pair cap

__device__ __forceinline__ void load_chunk(uint32_t sbase, int buf, int kslice, int e,
                                           const unsigned* s_tok)
{
    int tid = threadIdx.x;
    uint32_t a_s = sbase + OFF_A + buf * 16384;
    uint32_t b_s = sbase + OFF_B + buf * 32768;

    // A: 128 rows x 128B = 1024 16B units
#pragma unroll
    for (int i = 0; i < 4; i++) {
        int u = tid + i * GEMM_THREADS;
        int r = u >> 3, q8 = u & 7;
        unsigned tok = s_tok[r];
        size_t g = (size_t)tok * DDIM + kslice * 64 + q8 * 8;
        uint32_t d = a_s + (uint32_t)(r * 128 + ((q8 ^ (r & 7)) << 4));
        CP_ASYNC16(d, g_xh + g);
    }
    // B: 256 rows x 128B = 2048 16B units
#pragma unroll
    for (int i = 0; i < 8; i++) {
        int u = tid + i * GEMM_THREADS;
        int h = u >> 3, q8 = u & 7;
        size_t g = (size_t)e * (HDIM * DDIM) + (size_t)h * DDIM + kslice * 64 + q8 * 8;
        uint32_t d = b_s + (uint32_t)(h * 128 + ((q8 ^ (h & 7)) << 4));
        CP_ASYNC16(d, g_wh + g);
    }
}

__global__ __launch_bounds__(GEMM_THREADS, 1) void moe_gemm_kernel(
    const float* __restrict__ eb, float* __restrict__ out)
{
    int pid = blockIdx.y;
    unsigned cnt = g_pcnt[pid];
    unsigned row0 = blockIdx.x * 128u;
    if (row0 >= cnt) return;
    int rows = (int)min(128u, cnt - row0);
    int ep = c_pair_p[pid], eq = c_pair_q[pid];

    extern __shared__ char smem[];
    uint32_t sbase = smem_u32(smem);
    unsigned* s_tok = (unsigned*)(smem + OFF_TOK);
    float*    s_gp  = (float*)(smem + OFF_GP);
    float*    s_gq  = (float*)(smem + OFF_GQ);
    float*    s_bp  = (float*)(smem + OFF_BP);
    float*    s_bq  = (float*)(smem + OFF_BQ);

    int tid = threadIdx.x, wid = tid >> 5, lane = tid & 31;

    if (tid < 128) {
        bool v = (tid < rows);
        s_tok[tid] = v ? g_ptok[pid][row0 + tid] : 0u;
        s_gp [tid] = v ? g_pgp[pid][row0 + tid] : 0.f;
        s_gq [tid] = v ? g_pgq[pid][row0 + tid] : 1.f;   // keep ratio finite
    }
    s_bp[tid] = eb[ep * HDIM + tid];
    s_bq[tid] = eb[eq * HDIM + tid];
    __syncthreads();

    // 3-stage pipeline: preload chunks 0,1,2 (expert p)
    load_chunk(sbase, 0, 0, ep, s_tok); CP_COMMIT();
    load_chunk(sbase, 1, 1, ep, s_tok); CP_COMMIT();
    load_chunk(sbase, 2, 2, ep, s_tok); CP_COMMIT();

    // warp tile: 2 (M) x 4 (N) -> 64 rows x 64 cols per warp
    int warp_m = wid & 1;
    int warp_n = wid >> 1;

    // ldmatrix lane address components (PTX fragment layouts)
    int laneA_row = (lane & 7) + (((lane >> 3) & 1) << 3);
    int laneA_q   = (lane >> 4) & 1;
    int laneB_n   = (lane & 7) + (((lane >> 4) & 1) << 3);
    int laneB_q   = (lane >> 3) & 1;
    int grp = lane >> 2, tig = lane & 3;

    float acc[4][8][4];
#pragma unroll
    for (int a = 0; a < 4; a++)
#pragma unroll
        for (int b = 0; b < 8; b++)
#pragma unroll
            for (int d = 0; d < 4; d++) acc[a][b][d] = 0.f;

#pragma unroll 1
    for (int c = 0; c < 8; c++) {
        int buf = c % 3;
        if (c >= 6) { CP_WAIT(0); } else { CP_WAIT(2); }
        __syncthreads();

        uint32_t aBase = sbase + OFF_A + buf * 16384;
        uint32_t bBase = sbase + OFF_B + buf * 32768;

#pragma unroll
        for (int ks = 0; ks < 4; ks++) {
            uint32_t ahf[4][4];
#pragma unroll
            for (int mf = 0; mf < 4; mf++) {
                int r = warp_m * 64 + mf * 16 + laneA_row;
                int q8 = ks * 2 + laneA_q;
                uint32_t off = (uint32_t)(r * 128 + ((q8 ^ (r & 7)) << 4));
                ldsm4(aBase + off, ahf[mf]);
            }
#pragma unroll
            for (int nf = 0; nf < 4; nf++) {
                int n = warp_n * 64 + nf * 16 + laneB_n;
                int q8 = ks * 2 + laneB_q;
                uint32_t off = (uint32_t)(n * 128 + ((q8 ^ (n & 7)) << 4));
                uint32_t bh[4];
                ldsm4(bBase + off, bh);
                // 8 distinct accum frags between reuses
#pragma unroll
                for (int mf = 0; mf < 4; mf++) {
                    mma16816(acc[mf][2 * nf],     ahf[mf], bh[0], bh[1]);
                    mma16816(acc[mf][2 * nf + 1], ahf[mf], bh[2], bh[3]);
                }
            }
        }

        // Between the two expert sweeps: acc *= g_p/g_q per row
        if (c == 3) {
#pragma unroll
            for (int mf = 0; mf < 4; mf++) {
#pragma unroll
                for (int half = 0; half < 2; half++) {
                    int r = warp_m * 64 + mf * 16 + grp + half * 8;
                    float f = s_gp[r] / s_gq[r];
#pragma unroll
                    for (int nf = 0; nf < 8; nf++) {
                        acc[mf][nf][half * 2 + 0] *= f;
                        acc[mf][nf][half * 2 + 1] *= f;
                    }
                }
            }
        }

        __syncthreads();
        if (c < 5) {
            int nc = c + 3;
            load_chunk(sbase, buf, nc & 3, (nc < 4) ? ep : eq, s_tok);
            CP_COMMIT();
        }
    }

    // Epilogue: out[tok] = g_q*acc + g_p*b_p + g_q*b_q  (direct)
#pragma unroll
    for (int mf = 0; mf < 4; mf++) {
#pragma unroll
        for (int half = 0; half < 2; half++) {
            int r = warp_m * 64 + mf * 16 + grp + half * 8;
            if (r < rows) {
                unsigned tok = s_tok[r];
                float gq = s_gq[r], gp = s_gp[r];
                float* dst = out + (size_t)tok * HDIM;
#pragma unroll
                for (int nf = 0; nf < 8; nf++) {
                    int col = warp_n * 64 + nf * 8 + tig * 2;
                    float2 v;
                    v.x = gq * acc[mf][nf][half * 2 + 0] + gp * s_bp[col]     + gq * s_bq[col];
                    v.y = gq * acc[mf][nf][half * 2 + 1] + gp * s_bp[col + 1] + gq * s_bq[col + 1];
                    *(float2*)(dst + col) = v;
                }
            }
        }
    }
}

// ============================================================
// Launch
// ============================================================
extern "C" void kernel_launch(void* const* d_in, const int* in_sizes, int n_in,
                              void* d_out, int out_size)
{
    const float* x  = (const float*)d_in[0];
    const float* gw = (const float*)d_in[1];
    const float* gb = (const float*)d_in[2];
    const float* ew = (const float*)d_in[3];
    const float* eb = (const float*)d_in[4];
    float* out = (float*)d_out;

    cudaFuncSetAttribute(moe_gemm_kernel,
                         cudaFuncAttributeMaxDynamicSharedMemorySize, SMEM_TOTAL);

    reset_kernel<<<1, 32>>>();
    convert_w_kernel<<<(NEXP * HDIM * DDIM / 2) / 256, 256>>>(ew);
    gate_route_kernel<<<N_TOK / 8, 256>>>(x, gw, gb);
    moe_gemm_kernel<<<dim3(MAX_TILES, NPAIR), GEMM_THREADS, SMEM_TOTAL>>>(eb, out);
}

// round 10
// speedup vs baseline: 2.6052x; 1.0977x over previous
#include <cuda_runtime.h>
#include <cuda_fp16.h>
#include <cstdint>

// ============================================================
// Problem constants
// ============================================================
#define N_TOK  262144
#define DDIM   256
#define HDIM   256
#define NEXP   8
#define NPAIR  28

// ============================================================
// Device scratch (allocation-free contract: __device__ globals)
// ============================================================
__device__ unsigned g_pcnt[NPAIR];
__device__ unsigned g_ptok[NPAIR][N_TOK];   // token id per routed row
__device__ float    g_pgp [NPAIR][N_TOK];   // gate of lower-index expert p
__device__ float    g_pgq [NPAIR][N_TOK];   // gate of higher-index expert q
__device__ __half   g_xh[(size_t)N_TOK * DDIM];      // x in fp16
__device__ __half   g_wh[NEXP * HDIM * DDIM];        // W in fp16

// pair id -> expert indices
__device__ const int c_pair_p[NPAIR] =
    {0,0,0,0,0,0,0, 1,1,1,1,1,1, 2,2,2,2,2, 3,3,3,3, 4,4,4, 5,5, 6};
__device__ const int c_pair_q[NPAIR] =
    {1,2,3,4,5,6,7, 2,3,4,5,6,7, 3,4,5,6,7, 4,5,6,7, 5,6,7, 6,7, 7};

// ============================================================
// PTX helpers (plain sm_100 ONLY: cp.async, ldmatrix, mma.sync)
// ============================================================
__device__ __forceinline__ uint32_t smem_u32(const void* p) {
    uint32_t a;
    asm("{ .reg .u64 t; cvta.to.shared.u64 t, %1; cvt.u32.u64 %0, t; }" : "=r"(a) : "l"(p));
    return a;
}

#define CP_ASYNC16(dst, src) \
    asm volatile("cp.async.cg.shared.global [%0], [%1], 16;" :: "r"(dst), "l"(src))
#define CP_COMMIT() asm volatile("cp.async.commit_group;" ::: "memory")
#define CP_WAIT(n)  asm volatile("cp.async.wait_group %0;" :: "n"(n) : "memory")

__device__ __forceinline__ void ldsm4(uint32_t addr, uint32_t* r) {
    asm volatile("ldmatrix.sync.aligned.m8n8.x4.shared.b16 {%0,%1,%2,%3}, [%4];"
                 : "=r"(r[0]), "=r"(r[1]), "=r"(r[2]), "=r"(r[3]) : "r"(addr));
}

__device__ __forceinline__ void mma16816(float* c, const uint32_t* a,
                                         uint32_t b0, uint32_t b1) {
    asm volatile(
        "mma.sync.aligned.m16n8k16.row.col.f32.f16.f16.f32 "
        "{%0,%1,%2,%3}, {%4,%5,%6,%7}, {%8,%9}, {%0,%1,%2,%3};"
        : "+f"(c[0]), "+f"(c[1]), "+f"(c[2]), "+f"(c[3])
        : "r"(a[0]), "r"(a[1]), "r"(a[2]), "r"(a[3]), "r"(b0), "r"(b1));
}

// ============================================================
// Kernel 0: reset routing counters (graph-replay safe)
// ============================================================
__global__ void reset_kernel() {
    if (threadIdx.x < NPAIR) g_pcnt[threadIdx.x] = 0u;
}

// ============================================================
// Kernel 1: expert weights fp32 -> fp16
// ============================================================
__global__ void convert_w_kernel(const float* __restrict__ ew) {
    int i = blockIdx.x * 256 + threadIdx.x;           // pair index, total E*H*D/2
    float2 v = ((const float2*)ew)[i];
    __half2 h;
    h.x = __float2half_rn(v.x);
    h.y = __float2half_rn(v.y);
    ((__half2*)g_wh)[i] = h;
}

// ============================================================
// Kernel 2: gate + softmax + top-2 + pair routing + x -> fp16
//   one warp per token, 8 warps per block
// ============================================================
__global__ __launch_bounds__(256) void gate_route_kernel(
    const float* __restrict__ x,
    const float* __restrict__ gw,
    const float* __restrict__ gb)
{
    __shared__ float sgw[NEXP * DDIM];
    __shared__ float sgb[NEXP];
    for (int i = threadIdx.x; i < NEXP * DDIM; i += 256) sgw[i] = gw[i];
    if (threadIdx.x < NEXP) sgb[threadIdx.x] = gb[threadIdx.x];
    __syncthreads();

    int warp = threadIdx.x >> 5, lane = threadIdx.x & 31;
    int t = blockIdx.x * 8 + warp;

    const float2* xrow = (const float2*)(x + (size_t)t * DDIM);
    float2 xv[4];
#pragma unroll
    for (int j = 0; j < 4; j++) xv[j] = xrow[j * 32 + lane];

    // x -> fp16 (coalesced half2 stores)
    __half2* xh2 = (__half2*)(g_xh + (size_t)t * DDIM);
#pragma unroll
    for (int j = 0; j < 4; j++) {
        __half2 h;
        h.x = __float2half_rn(xv[j].x);
        h.y = __float2half_rn(xv[j].y);
        xh2[j * 32 + lane] = h;
    }

    // logits (fp32)
    float logit[NEXP];
#pragma unroll
    for (int e = 0; e < NEXP; e++) {
        float a = 0.f;
#pragma unroll
        for (int j = 0; j < 4; j++) {
            int c = j * 64 + lane * 2;
            a += xv[j].x * sgw[e * DDIM + c] + xv[j].y * sgw[e * DDIM + c + 1];
        }
#pragma unroll
        for (int o = 16; o; o >>= 1) a += __shfl_xor_sync(0xffffffffu, a, o);
        logit[e] = a + sgb[e];
    }

    // top-2 by logit (monotone with softmax prob; ties -> lowest index)
    int i0 = 0; float b0 = logit[0];
#pragma unroll
    for (int e = 1; e < NEXP; e++) if (logit[e] > b0) { b0 = logit[e]; i0 = e; }
    int i1 = -1; float b1 = -3.4e38f;
#pragma unroll
    for (int e = 0; e < NEXP; e++) if (e != i0 && logit[e] > b1) { b1 = logit[e]; i1 = e; }

    // softmax values for the two winners
    float s = 0.f;
#pragma unroll
    for (int e = 0; e < NEXP; e++) s += expf(logit[e] - b0);
    float inv = 1.f / s;
    float gv0 = expf(logit[i0] - b0) * inv;
    float gv1 = expf(logit[i1] - b0) * inv;

    if (lane == 0) {
        int p = min(i0, i1), q = max(i0, i1);
        float gp = (p == i0) ? gv0 : gv1;
        float gq = (p == i0) ? gv1 : gv0;
        int pid = p * 7 - (p * (p - 1)) / 2 + (q - p - 1);
        unsigned pos = atomicAdd(&g_pcnt[pid], 1u);
        g_ptok[pid][pos] = (unsigned)t;
        g_pgp [pid][pos] = gp;
        g_pgq [pid][pos] = gq;
    }
}

// ============================================================
// Kernel 3: pair-fused routed GEMM, single-term fp16 mma.sync
//   block = 128 tokens x ONE 128-col H-half of expert pair (p,q)
//   8 K-chunks (BK=64): 0-3 sweep W_p, 4-7 sweep W_q; accumulators
//   rescaled by g_p/g_q between sweeps; epilogue writes direct to out.
//   8 warps (256 thr) in 4(M)x2(N), warp tile 32x64, ~120 regs
//   -> __launch_bounds__(256,2): TWO CTAs per SM (independent
//   barrier domains overlap each other's sync/load windows).
//   3-stage cp.async pipeline, 32KB/stage, 100KB smem/CTA.
// ============================================================
static constexpr int OFF_TOK  = 0;      // 128 u32
static constexpr int OFF_GP   = 512;    // 128 f32
static constexpr int OFF_GQ   = 1024;   // 128 f32
static constexpr int OFF_BP   = 1536;   // 128 f32 (this half)
static constexpr int OFF_BQ   = 2048;   // 128 f32 (this half)
static constexpr int OFF_A    = 4096;   // 3 bufs x 16KB
static constexpr int OFF_B    = 53248;  // 3 bufs x 16KB
static constexpr int SMEM_TOTAL = 102400;
#define GEMM_THREADS 256
#define MAX_TILES 256                    // 256*128 = 32768 tokens/pair cap

__device__ __forceinline__ void load_chunk(uint32_t sbase, int buf, int kslice,
                                           int e, int nhalf, const unsigned* s_tok)
{
    int tid = threadIdx.x;
    uint32_t a_s = sbase + OFF_A + buf * 16384;
    uint32_t b_s = sbase + OFF_B + buf * 16384;

    // A: 128 rows x 128B = 1024 16B units
#pragma unroll
    for (int i = 0; i < 4; i++) {
        int u = tid + i * GEMM_THREADS;
        int r = u >> 3, q8 = u & 7;
        unsigned tok = s_tok[r];
        size_t g = (size_t)tok * DDIM + kslice * 64 + q8 * 8;
        uint32_t d = a_s + (uint32_t)(r * 128 + ((q8 ^ (r & 7)) << 4));
        CP_ASYNC16(d, g_xh + g);
    }
    // B: 128 rows (this H-half) x 128B = 1024 16B units
#pragma unroll
    for (int i = 0; i < 4; i++) {
        int u = tid + i * GEMM_THREADS;
        int h = u >> 3, q8 = u & 7;
        size_t g = (size_t)e * (HDIM * DDIM) + (size_t)(nhalf * 128 + h) * DDIM
                 + kslice * 64 + q8 * 8;
        uint32_t d = b_s + (uint32_t)(h * 128 + ((q8 ^ (h & 7)) << 4));
        CP_ASYNC16(d, g_wh + g);
    }
}

__global__ __launch_bounds__(GEMM_THREADS, 2) void moe_gemm_kernel(
    const float* __restrict__ eb, float* __restrict__ out)
{
    int pid = blockIdx.y;
    int nhalf = blockIdx.x & 1;
    unsigned tile = blockIdx.x >> 1;
    unsigned cnt = g_pcnt[pid];
    unsigned row0 = tile * 128u;
    if (row0 >= cnt) return;
    int rows = (int)min(128u, cnt - row0);
    int ep = c_pair_p[pid], eq = c_pair_q[pid];

    extern __shared__ char smem[];
    uint32_t sbase = smem_u32(smem);
    unsigned* s_tok = (unsigned*)(smem + OFF_TOK);
    float*    s_gp  = (float*)(smem + OFF_GP);
    float*    s_gq  = (float*)(smem + OFF_GQ);
    float*    s_bp  = (float*)(smem + OFF_BP);
    float*    s_bq  = (float*)(smem + OFF_BQ);

    int tid = threadIdx.x, wid = tid >> 5, lane = tid & 31;

    if (tid < 128) {
        bool v = (tid < rows);
        s_tok[tid] = v ? g_ptok[pid][row0 + tid] : 0u;
        s_gp [tid] = v ? g_pgp[pid][row0 + tid] : 0.f;
        s_gq [tid] = v ? g_pgq[pid][row0 + tid] : 1.f;   // keep ratio finite
    } else {
        int c0 = tid - 128;          // 0..127: bias for this H-half
        s_bp[c0] = eb[ep * HDIM + nhalf * 128 + c0];
        s_bq[c0] = eb[eq * HDIM + nhalf * 128 + c0];
    }
    __syncthreads();

    // 3-stage pipeline: preload chunks 0,1,2 (expert p)
    load_chunk(sbase, 0, 0, ep, nhalf, s_tok); CP_COMMIT();
    load_chunk(sbase, 1, 1, ep, nhalf, s_tok); CP_COMMIT();
    load_chunk(sbase, 2, 2, ep, nhalf, s_tok); CP_COMMIT();

    // warp tile: 4 (M) x 2 (N) -> 32 rows x 64 cols per warp
    int warp_m = wid & 3;
    int warp_n = wid >> 2;

    // ldmatrix lane address components (PTX fragment layouts)
    int laneA_row = (lane & 7) + (((lane >> 3) & 1) << 3);
    int laneA_q   = (lane >> 4) & 1;
    int laneB_n   = (lane & 7) + (((lane >> 4) & 1) << 3);
    int laneB_q   = (lane >> 3) & 1;
    int grp = lane >> 2, tig = lane & 3;

    float acc[2][8][4];
#pragma unroll
    for (int a = 0; a < 2; a++)
#pragma unroll
        for (int b = 0; b < 8; b++)
#pragma unroll
            for (int d = 0; d < 4; d++) acc[a][b][d] = 0.f;

#pragma unroll 1
    for (int c = 0; c < 8; c++) {
        int buf = c % 3;
        if (c >= 6) { CP_WAIT(0); } else { CP_WAIT(2); }
        __syncthreads();

        uint32_t aBase = sbase + OFF_A + buf * 16384;
        uint32_t bBase = sbase + OFF_B + buf * 16384;

#pragma unroll
        for (int ks = 0; ks < 4; ks++) {
            uint32_t ahf[2][4];
#pragma unroll
            for (int mf = 0; mf < 2; mf++) {
                int r = warp_m * 32 + mf * 16 + laneA_row;
                int q8 = ks * 2 + laneA_q;
                uint32_t off = (uint32_t)(r * 128 + ((q8 ^ (r & 7)) << 4));
                ldsm4(aBase + off, ahf[mf]);
            }
#pragma unroll
            for (int nf = 0; nf < 4; nf++) {
                int n = warp_n * 64 + nf * 16 + laneB_n;
                int q8 = ks * 2 + laneB_q;
                uint32_t off = (uint32_t)(n * 128 + ((q8 ^ (n & 7)) << 4));
                uint32_t bh[4];
                ldsm4(bBase + off, bh);
#pragma unroll
                for (int mf = 0; mf < 2; mf++) {
                    mma16816(acc[mf][2 * nf],     ahf[mf], bh[0], bh[1]);
                    mma16816(acc[mf][2 * nf + 1], ahf[mf], bh[2], bh[3]);
                }
            }
        }

        // Between the two expert sweeps: acc *= g_p/g_q per row
        if (c == 3) {
#pragma unroll
            for (int mf = 0; mf < 2; mf++) {
#pragma unroll
                for (int half = 0; half < 2; half++) {
                    int r = warp_m * 32 + mf * 16 + grp + half * 8;
                    float f = s_gp[r] / s_gq[r];
#pragma unroll
                    for (int nf = 0; nf < 8; nf++) {
                        acc[mf][nf][half * 2 + 0] *= f;
                        acc[mf][nf][half * 2 + 1] *= f;
                    }
                }
            }
        }

        __syncthreads();
        if (c < 5) {
            int nc = c + 3;
            load_chunk(sbase, buf, nc & 3, (nc < 4) ? ep : eq, nhalf, s_tok);
            CP_COMMIT();
        }
    }

    // Epilogue: out[tok, nhalf-half] = g_q*acc + g_p*b_p + g_q*b_q
#pragma unroll
    for (int mf = 0; mf < 2; mf++) {
#pragma unroll
        for (int half = 0; half < 2; half++) {
            int r = warp_m * 32 + mf * 16 + grp + half * 8;
            if (r < rows) {
                unsigned tok = s_tok[r];
                float gq = s_gq[r], gp = s_gp[r];
                float* dst = out + (size_t)tok * HDIM + nhalf * 128;
#pragma unroll
                for (int nf = 0; nf < 8; nf++) {
                    int col = warp_n * 64 + nf * 8 + tig * 2;
                    float2 v;
                    v.x = gq * acc[mf][nf][half * 2 + 0] + gp * s_bp[col]     + gq * s_bq[col];
                    v.y = gq * acc[mf][nf][half * 2 + 1] + gp * s_bp[col + 1] + gq * s_bq[col + 1];
                    *(float2*)(dst + col) = v;
                }
            }
        }
    }
}

// ============================================================
// Launch
// ============================================================
extern "C" void kernel_launch(void* const* d_in, const int* in_sizes, int n_in,
                              void* d_out, int out_size)
{
    const float* x  = (const float*)d_in[0];
    const float* gw = (const float*)d_in[1];
    const float* gb = (const float*)d_in[2];
    const float* ew = (const float*)d_in[3];
    const float* eb = (const float*)d_in[4];
    float* out = (float*)d_out;

    cudaFuncSetAttribute(moe_gemm_kernel,
                         cudaFuncAttributeMaxDynamicSharedMemorySize, SMEM_TOTAL);

    reset_kernel<<<1, 32>>>();
    convert_w_kernel<<<(NEXP * HDIM * DDIM / 2) / 256, 256>>>(ew);
    gate_route_kernel<<<N_TOK / 8, 256>>>(x, gw, gb);
    moe_gemm_kernel<<<dim3(MAX_TILES * 2, NPAIR), GEMM_THREADS, SMEM_TOTAL>>>(eb, out);
}